// round 15
// baseline (speedup 1.0000x reference)
#include <cuda_runtime.h>
#include <cuda_bf16.h>
#include <math.h>

// GPT-2 small forward: tf32 mma.sync GEMMs (pre-rounded operands; qkv GEMM epilogue
// emits pre-split bf16 hi/lo Q/K/V^T) + bf16-split tensor-core flash attention with
// pure-cp.async tile loads.
// B=2, T=1024, C=768, H=12, HD=64, L=12, V=50257.

#define Bsz 2
#define Tlen 1024
#define BT (Bsz * Tlen)      // 2048
#define C 768
#define H 12
#define HD 64
#define NL 12
#define V 50257
#define VP 50304
#define C3 (3 * C)           // 2304
#define C4 (4 * C)           // 3072
#define EPS 1e-5f

typedef __nv_bfloat16 bf16;

// ---------------- scratch ----------------
__device__ float g_x[BT * C];
__device__ float g_ln[BT * C];
__device__ float g_atty[BT * C];
__device__ float g_h[BT * C4];
__device__ float g_wpad[(long long)C * VP];
__device__ float g_wqkv[(long long)NL * C * C3];
__device__ float g_wproj[(long long)NL * C * C];
__device__ float g_wfc[(long long)NL * C * C4];
__device__ float g_wfp[(long long)NL * C4 * C];
// pre-split attention operands (per layer, reused): [b*H+h] major
#define QKVN (Bsz * H * Tlen * HD)   // 1,572,864
__device__ bf16 g_qh[QKVN], g_ql[QKVN];     // [bh][t][d], scaled 1/8
__device__ bf16 g_kh[QKVN], g_kl[QKVN];     // [bh][t][d]
__device__ bf16 g_vth[QKVN], g_vtl[QKVN];   // [bh][d][t] (transposed)

// ---------------- helpers ----------------
__device__ __forceinline__ float gelu_f(float x) {
    float x3 = x * x * x;
    return 0.5f * x * (1.f + tanhf(0.7978845608028654f * (x + 0.044715f * x3)));
}

__device__ __forceinline__ unsigned tf32_of(float f) {
    unsigned u;
    asm("cvt.rna.tf32.f32 %0, %1;" : "=r"(u) : "f"(f));
    return u;
}
__device__ __forceinline__ float tf32r(float f) { return __uint_as_float(tf32_of(f)); }

__device__ __forceinline__ unsigned sptr(const void* p) {
    return (unsigned)__cvta_generic_to_shared(p);
}

__device__ __forceinline__ unsigned packbf(float lo, float hi) {
    unsigned r;
    asm("cvt.rn.bf16x2.f32 %0, %1, %2;" : "=r"(r) : "f"(hi), "f"(lo));
    return r;
}
__device__ __forceinline__ float lof(float x) {
    return x - __bfloat162float(__float2bfloat16(x));
}

__device__ __forceinline__ void mma_bf16(float* c, const unsigned* a, const unsigned* b) {
    asm volatile("mma.sync.aligned.m16n8k16.row.col.f32.bf16.bf16.f32 "
                 "{%0,%1,%2,%3},{%4,%5,%6,%7},{%8,%9},{%0,%1,%2,%3};"
                 : "+f"(c[0]), "+f"(c[1]), "+f"(c[2]), "+f"(c[3])
                 : "r"(a[0]), "r"(a[1]), "r"(a[2]), "r"(a[3]), "r"(b[0]), "r"(b[1]));
}
__device__ __forceinline__ void ldsm4(unsigned* r, unsigned addr) {
    asm volatile("ldmatrix.sync.aligned.m8n8.x4.shared.b16 {%0,%1,%2,%3}, [%4];"
                 : "=r"(r[0]), "=r"(r[1]), "=r"(r[2]), "=r"(r[3]) : "r"(addr));
}

// ---------------- embedding ----------------
__global__ void embed_kernel(const int* __restrict__ idx,
                             const float* __restrict__ wte,
                             const float* __restrict__ wpe,
                             float* __restrict__ out) {
    int row = blockIdx.x;
    int tpos = row % Tlen;
    int tok = idx[row];
    const float* we = wte + (long long)tok * C;
    const float* pe = wpe + (long long)tpos * C;
    float* o = out + (long long)row * C;
    for (int c = threadIdx.x; c < C; c += blockDim.x)
        o[c] = we[c] + pe[c];
}

// ---------------- weight pre-rounding ----------------
__global__ void cvtw_kernel(const float* __restrict__ w, float* __restrict__ o, long long n4) {
    long long i = (long long)blockIdx.x * blockDim.x + threadIdx.x;
    if (i < n4) {
        float4 v = ((const float4*)w)[i];
        v.x = tf32r(v.x); v.y = tf32r(v.y); v.z = tf32r(v.z); v.w = tf32r(v.w);
        ((float4*)o)[i] = v;
    }
}

// ---------------- lm_head pad + round ----------------
__global__ void padw_kernel(const float* __restrict__ w, float* __restrict__ wp) {
    int k = blockIdx.y;
    int n = blockIdx.x * blockDim.x + threadIdx.x;
    if (n < VP)
        wp[(long long)k * VP + n] = (n < V) ? tf32r(w[(long long)k * V + n]) : 0.f;
}

// ---------------- layernorm (tf32-rounded output) ----------------
__global__ void ln_kernel(const float* __restrict__ x,
                          const float* __restrict__ w,
                          const float* __restrict__ b,
                          float* __restrict__ out) {
    __shared__ float red[256];
    __shared__ float red2[256];
    int row = blockIdx.x;
    const float* xr = x + (long long)row * C;
    float s = 0.f, sq = 0.f;
    for (int c = threadIdx.x; c < C; c += blockDim.x) {
        float v = xr[c];
        s += v; sq += v * v;
    }
    red[threadIdx.x] = s; red2[threadIdx.x] = sq;
    __syncthreads();
    for (int off = 128; off > 0; off >>= 1) {
        if (threadIdx.x < off) {
            red[threadIdx.x] += red[threadIdx.x + off];
            red2[threadIdx.x] += red2[threadIdx.x + off];
        }
        __syncthreads();
    }
    float mean = red[0] / C;
    float var = red2[0] / C - mean * mean;
    float rstd = rsqrtf(var + EPS);
    float* o = out + (long long)row * C;
    for (int c = threadIdx.x; c < C; c += blockDim.x)
        o[c] = tf32r((xr[c] - mean) * rstd * w[c] + b[c]);
}

// ---------------- 3-stage cp.async tf32 GEMM ----------------
// epi: 0=+bias, 1=gelu->round, 2=+bias+residual, 3=none, 4=qkv split (bf16 hi/lo Q/K/V^T)
#define ASTR 20
#define BSTR 136

template<int BM>
__global__ void __launch_bounds__(256, 2)
tgemm_kernel(const float* __restrict__ A, const float* __restrict__ W,
             const float* __restrict__ bias, float* __restrict__ out,
             int M, int N, int K, int ldw, int epi,
             bf16* qh, bf16* ql, bf16* kh, bf16* kl, bf16* vth, bf16* vtl) {
    constexpr int MI = BM / 32;
    extern __shared__ float sm[];
    float* As = sm;
    float* Bs = sm + 3 * BM * ASTR;

    int tid = threadIdx.x;
    int w = tid >> 5, lane = tid & 31;
    int g = lane >> 2, tig = lane & 3;
    int wm = (w & 1) * (BM / 2);
    int wn = (w >> 1) * 32;
    int m0 = blockIdx.y * BM;
    int n0 = blockIdx.x * 128;

    float acc[MI][4][4];
#pragma unroll
    for (int mi = 0; mi < MI; mi++)
#pragma unroll
        for (int nj = 0; nj < 4; nj++)
#pragma unroll
            for (int r = 0; r < 4; r++) acc[mi][nj][r] = 0.f;

    auto loadTiles = [&](int kt, int s) {
        int k0 = kt * 16;
        float* as = As + s * (BM * ASTR);
        float* bs = Bs + s * (16 * BSTR);
#pragma unroll
        for (int i = 0; i < BM / 64; i++) {
            int id = tid + i * 256;
            int row = id >> 2, kc = (id & 3) * 4;
            unsigned dst = sptr(&as[row * ASTR + kc]);
            const float* src = A + (long long)(m0 + row) * K + k0 + kc;
            asm volatile("cp.async.cg.shared.global [%0], [%1], 16;" :: "r"(dst), "l"(src));
        }
#pragma unroll
        for (int i = 0; i < 2; i++) {
            int id = tid + i * 256;
            int row = id >> 5, nc = (id & 31) * 4;
            unsigned dst = sptr(&bs[row * BSTR + nc]);
            const float* src = W + (long long)(k0 + row) * ldw + n0 + nc;
            asm volatile("cp.async.cg.shared.global [%0], [%1], 16;" :: "r"(dst), "l"(src));
        }
    };

    int nk = K / 16;
    loadTiles(0, 0);
    asm volatile("cp.async.commit_group;");
    loadTiles(1, 1);
    asm volatile("cp.async.commit_group;");

    for (int kt = 0; kt < nk; kt++) {
        asm volatile("cp.async.wait_group 1;");
        __syncthreads();

        if (kt + 2 < nk) loadTiles(kt + 2, (kt + 2) % 3);
        asm volatile("cp.async.commit_group;");

        int cur = kt % 3;
        const float* as = As + cur * (BM * ASTR);
        const float* bs = Bs + cur * (16 * BSTR);

#pragma unroll
        for (int kk = 0; kk < 2; kk++) {
            unsigned af[MI][4], bf[4][2];
#pragma unroll
            for (int mi = 0; mi < MI; mi++) {
                int r = wm + mi * 16 + g;
                af[mi][0] = __float_as_uint(as[r * ASTR + kk * 8 + tig]);
                af[mi][1] = __float_as_uint(as[(r + 8) * ASTR + kk * 8 + tig]);
                af[mi][2] = __float_as_uint(as[r * ASTR + kk * 8 + tig + 4]);
                af[mi][3] = __float_as_uint(as[(r + 8) * ASTR + kk * 8 + tig + 4]);
            }
#pragma unroll
            for (int nj = 0; nj < 4; nj++) {
                int col = wn + nj * 8 + g;
                bf[nj][0] = __float_as_uint(bs[(kk * 8 + tig) * BSTR + col]);
                bf[nj][1] = __float_as_uint(bs[(kk * 8 + tig + 4) * BSTR + col]);
            }
#pragma unroll
            for (int mi = 0; mi < MI; mi++)
#pragma unroll
                for (int nj = 0; nj < 4; nj++)
                    asm volatile(
                        "mma.sync.aligned.m16n8k8.row.col.f32.tf32.tf32.f32 "
                        "{%0,%1,%2,%3},{%4,%5,%6,%7},{%8,%9},{%0,%1,%2,%3};\n"
                        : "+f"(acc[mi][nj][0]), "+f"(acc[mi][nj][1]),
                          "+f"(acc[mi][nj][2]), "+f"(acc[mi][nj][3])
                        : "r"(af[mi][0]), "r"(af[mi][1]), "r"(af[mi][2]), "r"(af[mi][3]),
                          "r"(bf[nj][0]), "r"(bf[nj][1]));
        }
    }

#pragma unroll
    for (int mi = 0; mi < MI; mi++) {
        int r0 = m0 + wm + mi * 16 + g;
#pragma unroll
        for (int nj = 0; nj < 4; nj++) {
            int col = n0 + wn + nj * 8 + 2 * tig;
#pragma unroll
            for (int half = 0; half < 2; half++) {
                int rr = r0 + half * 8;
#pragma unroll
                for (int jj = 0; jj < 2; jj++) {
                    int cc = col + jj;
                    if (cc < N) {
                        float v = acc[mi][nj][half * 2 + jj];
                        if (epi != 3) v += bias[cc];
                        if (epi == 4) {
                            // qkv split epilogue
                            int t = rr & (Tlen - 1);
                            int bb = rr >> 10;
                            int sec = cc / C;
                            int wi = cc - sec * C;
                            long long bh = (long long)(bb * H + (wi >> 6));
                            int d = wi & 63;
                            if (sec == 0) {
                                float q = v * 0.125f;
                                long long o2 = (bh * Tlen + t) * HD + d;
                                qh[o2] = __float2bfloat16(q);
                                ql[o2] = __float2bfloat16(lof(q));
                            } else if (sec == 1) {
                                long long o2 = (bh * Tlen + t) * HD + d;
                                kh[o2] = __float2bfloat16(v);
                                kl[o2] = __float2bfloat16(lof(v));
                            } else {
                                long long o2 = (bh * HD + d) * Tlen + t;
                                vth[o2] = __float2bfloat16(v);
                                vtl[o2] = __float2bfloat16(lof(v));
                            }
                        } else {
                            if (epi == 1) v = tf32r(gelu_f(v));
                            long long o = (long long)rr * N + cc;
                            if (epi == 2) v += out[o];
                            out[o] = v;
                        }
                    }
                }
            }
        }
    }
}

// ---------------- tensor-core flash attention (pre-split bf16, cp.async loads) ----------------
// Block: 64 q x 1 head, 128 threads (4 warps; warp w -> q rows w*16..w*16+15).
// kv tiles of 64. All operands pre-split bf16 in gmem; tile loads are pure cp.async.
// Fragment/mma math identical to validated R13.
#define FAST 72   // bf16 row stride (144B = 9x16B): cp.async-aligned, ldmatrix conflict-free

__global__ void __launch_bounds__(128)
fattn_kernel(const bf16* __restrict__ qh, const bf16* __restrict__ ql,
             const bf16* __restrict__ kh, const bf16* __restrict__ kl,
             const bf16* __restrict__ vth, const bf16* __restrict__ vtl,
             float* __restrict__ out) {
    extern __shared__ __align__(16) bf16 smb[];
    bf16* sQh = smb;
    bf16* sQl = sQh + 64 * FAST;
    bf16* sKh = sQl + 64 * FAST;
    bf16* sKl = sKh + 64 * FAST;
    bf16* sVh = sKl + 64 * FAST;   // [d][t]
    bf16* sVl = sVh + 64 * FAST;

    int tid = threadIdx.x;
    int w = tid >> 5, lane = tid & 31;
    int g = lane >> 2, tig = lane & 3;
    int qt = (int)gridDim.x - 1 - (int)blockIdx.x;  // heavy tiles first
    int h = blockIdx.y, b = blockIdx.z;
    int q0 = qt * 64;
    long long bh = (long long)(b * H + h);

    // ---- prologue: cp.async Q hi/lo ----
    {
        int row = tid & 63;
        const bf16* src = ((tid >> 6) ? ql : qh) + (bh * Tlen + q0 + row) * HD;
        bf16* db = (tid >> 6) ? sQl : sQh;
        unsigned dst = sptr(db) + (unsigned)(row * FAST) * 2u;
#pragma unroll
        for (int j = 0; j < 8; j++)
            asm volatile("cp.async.cg.shared.global [%0], [%1], 16;"
                         :: "r"(dst + j * 16), "l"(src + j * 8));
        asm volatile("cp.async.commit_group;");
        asm volatile("cp.async.wait_group 0;");
    }
    __syncthreads();

    // ---- Q fragments ----
    unsigned aQh[4][4], aQl[4][4];
    {
        int arow = w * 16 + (lane & 15);
        int acol8 = (lane >> 4) << 3;
        unsigned qaH = sptr(sQh) + (unsigned)(arow * FAST + acol8) * 2;
        unsigned qaL = sptr(sQl) + (unsigned)(arow * FAST + acol8) * 2;
#pragma unroll
        for (int kk = 0; kk < 4; kk++) {
            ldsm4(aQh[kk], qaH + kk * 32);
            ldsm4(aQl[kk], qaL + kk * 32);
        }
    }

    int brow_off = (lane & 7) + ((lane & 16) ? 8 : 0);
    int bcol_off = (lane & 8) ? 8 : 0;
    unsigned kbH = sptr(sKh) + (unsigned)(brow_off * FAST + bcol_off) * 2;
    unsigned kbL = sptr(sKl) + (unsigned)(brow_off * FAST + bcol_off) * 2;
    unsigned vbH = sptr(sVh) + (unsigned)(brow_off * FAST + bcol_off) * 2;
    unsigned vbL = sptr(sVl) + (unsigned)(brow_off * FAST + bcol_off) * 2;
    const unsigned PSTEP = 16u * FAST * 2u;

    float of[8][4];
#pragma unroll
    for (int nj = 0; nj < 8; nj++)
#pragma unroll
        for (int r = 0; r < 4; r++) of[nj][r] = 0.f;
    float ls0 = 0.f, ls1 = 0.f;

    int qg0 = q0 + w * 16 + g;
    int qg1 = qg0 + 8;
    int ntiles = qt + 1;

    for (int kt = 0; kt < ntiles; kt++) {
        int kv0 = kt * 64;
        __syncthreads();
        // ---- cp.async K hi/lo + V^T hi/lo (2 row-jobs per thread) ----
        {
            int job = tid;
#pragma unroll
            for (int rep = 0; rep < 2; rep++, job += 128) {
                int row = job & 63;
                int sel = job >> 6;
                const bf16* src;
                bf16* db;
                if (sel == 0)      { src = kh  + (bh * Tlen + kv0 + row) * HD; db = sKh; }
                else if (sel == 1) { src = kl  + (bh * Tlen + kv0 + row) * HD; db = sKl; }
                else if (sel == 2) { src = vth + (bh * HD + row) * Tlen + kv0; db = sVh; }
                else               { src = vtl + (bh * HD + row) * Tlen + kv0; db = sVl; }
                unsigned dst = sptr(db) + (unsigned)(row * FAST) * 2u;
#pragma unroll
                for (int j = 0; j < 8; j++)
                    asm volatile("cp.async.cg.shared.global [%0], [%1], 16;"
                                 :: "r"(dst + j * 16), "l"(src + j * 8));
            }
            asm volatile("cp.async.commit_group;");
            asm volatile("cp.async.wait_group 0;");
        }
        __syncthreads();

        // ---- S = Q @ K^T (3-term) ----
        float c[8][4];
#pragma unroll
        for (int nj = 0; nj < 8; nj++)
#pragma unroll
            for (int r = 0; r < 4; r++) c[nj][r] = 0.f;

#pragma unroll
        for (int kk = 0; kk < 4; kk++) {
            unsigned bhf[8][2], blf[8][2], t[4];
#pragma unroll
            for (int p = 0; p < 4; p++) {
                ldsm4(t, kbH + p * PSTEP + kk * 32);
                bhf[2 * p][0] = t[0]; bhf[2 * p][1] = t[1];
                bhf[2 * p + 1][0] = t[2]; bhf[2 * p + 1][1] = t[3];
                ldsm4(t, kbL + p * PSTEP + kk * 32);
                blf[2 * p][0] = t[0]; blf[2 * p][1] = t[1];
                blf[2 * p + 1][0] = t[2]; blf[2 * p + 1][1] = t[3];
            }
#pragma unroll
            for (int nj = 0; nj < 8; nj++) {
                mma_bf16(c[nj], aQh[kk], bhf[nj]);
                mma_bf16(c[nj], aQh[kk], blf[nj]);
                mma_bf16(c[nj], aQl[kk], bhf[nj]);
            }
        }

        // ---- fixed-shift softmax on fragments ----
        bool diag = (kt == qt);
#pragma unroll
        for (int nj = 0; nj < 8; nj++) {
            int colb = kv0 + 8 * nj + 2 * tig;
            float p0 = __expf(c[nj][0]);
            float p1 = __expf(c[nj][1]);
            float p2 = __expf(c[nj][2]);
            float p3 = __expf(c[nj][3]);
            if (diag) {
                if (colb > qg0)     p0 = 0.f;
                if (colb + 1 > qg0) p1 = 0.f;
                if (colb > qg1)     p2 = 0.f;
                if (colb + 1 > qg1) p3 = 0.f;
            }
            c[nj][0] = p0; c[nj][1] = p1; c[nj][2] = p2; c[nj][3] = p3;
            ls0 += p0 + p1;
            ls1 += p2 + p3;
        }

        // ---- O += P @ V (3-term) ----
#pragma unroll
        for (int kk = 0; kk < 4; kk++) {
            unsigned aph[4], apl[4];
            aph[0] = packbf(c[2 * kk][0], c[2 * kk][1]);
            aph[1] = packbf(c[2 * kk][2], c[2 * kk][3]);
            aph[2] = packbf(c[2 * kk + 1][0], c[2 * kk + 1][1]);
            aph[3] = packbf(c[2 * kk + 1][2], c[2 * kk + 1][3]);
            apl[0] = packbf(lof(c[2 * kk][0]), lof(c[2 * kk][1]));
            apl[1] = packbf(lof(c[2 * kk][2]), lof(c[2 * kk][3]));
            apl[2] = packbf(lof(c[2 * kk + 1][0]), lof(c[2 * kk + 1][1]));
            apl[3] = packbf(lof(c[2 * kk + 1][2]), lof(c[2 * kk + 1][3]));

            unsigned vh[8][2], vl[8][2], t[4];
#pragma unroll
            for (int p = 0; p < 4; p++) {
                ldsm4(t, vbH + p * PSTEP + kk * 32);
                vh[2 * p][0] = t[0]; vh[2 * p][1] = t[1];
                vh[2 * p + 1][0] = t[2]; vh[2 * p + 1][1] = t[3];
                ldsm4(t, vbL + p * PSTEP + kk * 32);
                vl[2 * p][0] = t[0]; vl[2 * p][1] = t[1];
                vl[2 * p + 1][0] = t[2]; vl[2 * p + 1][1] = t[3];
            }
#pragma unroll
            for (int nj = 0; nj < 8; nj++) {
                mma_bf16(of[nj], aph, vh[nj]);
                mma_bf16(of[nj], apl, vh[nj]);
                mma_bf16(of[nj], aph, vl[nj]);
            }
        }
    }

    // ---- l reduction across tig lanes ----
    ls0 += __shfl_xor_sync(0xFFFFFFFFu, ls0, 1);
    ls0 += __shfl_xor_sync(0xFFFFFFFFu, ls0, 2);
    ls1 += __shfl_xor_sync(0xFFFFFFFFu, ls1, 1);
    ls1 += __shfl_xor_sync(0xFFFFFFFFu, ls1, 2);
    float inv0 = 1.f / ls0;
    float inv1 = 1.f / ls1;

    long long r0 = (long long)(b * Tlen + qg0) * C + h * HD;
    long long r1 = (long long)(b * Tlen + qg1) * C + h * HD;
#pragma unroll
    for (int nj = 0; nj < 8; nj++) {
        int col = 8 * nj + 2 * tig;
        float2 v0, v1;
        v0.x = tf32r(of[nj][0] * inv0); v0.y = tf32r(of[nj][1] * inv0);
        v1.x = tf32r(of[nj][2] * inv1); v1.y = tf32r(of[nj][3] * inv1);
        *(float2*)&out[r0 + col] = v0;
        *(float2*)&out[r1 + col] = v1;
    }
}

// ---------------- driver ----------------
#define GEMM_SMEM(BM) (3 * ((BM) * ASTR + 16 * BSTR) * (int)sizeof(float))
#define ATTN_SMEM (6 * 64 * FAST * (int)sizeof(bf16))

extern "C" void kernel_launch(void* const* d_in, const int* in_sizes, int n_in,
                              void* d_out, int out_size) {
    const int*   idx      = (const int*)  d_in[0];
    const float* wte      = (const float*)d_in[1];
    const float* wpe      = (const float*)d_in[2];
    const float* ln1_w    = (const float*)d_in[3];
    const float* ln1_b    = (const float*)d_in[4];
    const float* attn_w   = (const float*)d_in[5];
    const float* attn_b   = (const float*)d_in[6];
    const float* proj_w   = (const float*)d_in[7];
    const float* proj_b   = (const float*)d_in[8];
    const float* ln2_w    = (const float*)d_in[9];
    const float* ln2_b    = (const float*)d_in[10];
    const float* fc_w     = (const float*)d_in[11];
    const float* fc_b     = (const float*)d_in[12];
    const float* fcproj_w = (const float*)d_in[13];
    const float* fcproj_b = (const float*)d_in[14];
    const float* lnf_w    = (const float*)d_in[15];
    const float* lnf_b    = (const float*)d_in[16];
    const float* lm_head  = (const float*)d_in[17];
    float* out = (float*)d_out;

    float *x, *ln, *atty, *hbuf, *wpad, *wq, *wp, *wf, *wfp;
    bf16 *qh, *ql, *kh, *kl, *vth, *vtl;
    cudaGetSymbolAddress((void**)&x,    g_x);
    cudaGetSymbolAddress((void**)&ln,   g_ln);
    cudaGetSymbolAddress((void**)&atty, g_atty);
    cudaGetSymbolAddress((void**)&hbuf, g_h);
    cudaGetSymbolAddress((void**)&wpad, g_wpad);
    cudaGetSymbolAddress((void**)&wq,   g_wqkv);
    cudaGetSymbolAddress((void**)&wp,   g_wproj);
    cudaGetSymbolAddress((void**)&wf,   g_wfc);
    cudaGetSymbolAddress((void**)&wfp,  g_wfp);
    cudaGetSymbolAddress((void**)&qh,   g_qh);
    cudaGetSymbolAddress((void**)&ql,   g_ql);
    cudaGetSymbolAddress((void**)&kh,   g_kh);
    cudaGetSymbolAddress((void**)&kl,   g_kl);
    cudaGetSymbolAddress((void**)&vth,  g_vth);
    cudaGetSymbolAddress((void**)&vtl,  g_vtl);

    cudaFuncSetAttribute(tgemm_kernel<128>,
                         cudaFuncAttributeMaxDynamicSharedMemorySize, GEMM_SMEM(128));
    cudaFuncSetAttribute(tgemm_kernel<64>,
                         cudaFuncAttributeMaxDynamicSharedMemorySize, GEMM_SMEM(64));
    cudaFuncSetAttribute(fattn_kernel,
                         cudaFuncAttributeMaxDynamicSharedMemorySize, ATTN_SMEM);

    {
        long long n4;
        n4 = (long long)NL * C * C3 / 4;
        cvtw_kernel<<<(int)((n4 + 255) / 256), 256>>>(attn_w, wq, n4);
        n4 = (long long)NL * C * C / 4;
        cvtw_kernel<<<(int)((n4 + 255) / 256), 256>>>(proj_w, wp, n4);
        n4 = (long long)NL * C * C4 / 4;
        cvtw_kernel<<<(int)((n4 + 255) / 256), 256>>>(fc_w, wf, n4);
        n4 = (long long)NL * C4 * C / 4;
        cvtw_kernel<<<(int)((n4 + 255) / 256), 256>>>(fcproj_w, wfp, n4);
    }
    padw_kernel<<<dim3((VP + 255) / 256, C), 256>>>(lm_head, wpad);
    embed_kernel<<<BT, 256>>>(idx, wte, wpe, x);

    for (int l = 0; l < NL; l++) {
        ln_kernel<<<BT, 256>>>(x, ln1_w + l * C, ln1_b + l * C, ln);
        tgemm_kernel<128><<<dim3(C3 / 128, BT / 128), 256, GEMM_SMEM(128)>>>(
            ln, wq + (long long)l * C * C3, attn_b + l * C3, nullptr, BT, C3, C, C3, 4,
            qh, ql, kh, kl, vth, vtl);
        fattn_kernel<<<dim3(Tlen / 64, H, Bsz), 128, ATTN_SMEM>>>(
            qh, ql, kh, kl, vth, vtl, atty);
        tgemm_kernel<64><<<dim3(C / 128, BT / 64), 256, GEMM_SMEM(64)>>>(
            atty, wp + (long long)l * C * C, proj_b + l * C, x, BT, C, C, C, 2,
            nullptr, nullptr, nullptr, nullptr, nullptr, nullptr);
        ln_kernel<<<BT, 256>>>(x, ln2_w + l * C, ln2_b + l * C, ln);
        tgemm_kernel<128><<<dim3(C4 / 128, BT / 128), 256, GEMM_SMEM(128)>>>(
            ln, wf + (long long)l * C * C4, fc_b + l * C4, hbuf, BT, C4, C, C4, 1,
            nullptr, nullptr, nullptr, nullptr, nullptr, nullptr);
        tgemm_kernel<64><<<dim3(C / 128, BT / 64), 256, GEMM_SMEM(64)>>>(
            hbuf, wfp + (long long)l * C4 * C, fcproj_b + l * C, x, BT, C, C4, C, 2,
            nullptr, nullptr, nullptr, nullptr, nullptr, nullptr);
    }

    ln_kernel<<<BT, 256>>>(x, lnf_w, lnf_b, ln);
    tgemm_kernel<128><<<dim3(VP / 128, BT / 128), 256, GEMM_SMEM(128)>>>(
        ln, wpad, (const float*)nullptr, out, BT, V, C, VP, 3,
        nullptr, nullptr, nullptr, nullptr, nullptr, nullptr);
}

// round 16
// speedup vs baseline: 1.0070x; 1.0070x over previous
#include <cuda_runtime.h>
#include <cuda_bf16.h>
#include <math.h>

// GPT-2 small forward: tf32 mma.sync GEMMs (pre-rounded operands; qkv GEMM epilogue
// emits pre-split bf16 hi/lo Q/K/V^T) + bf16-split tensor-core flash attention with
// double-buffered cp.async kv pipeline.
// B=2, T=1024, C=768, H=12, HD=64, L=12, V=50257.

#define Bsz 2
#define Tlen 1024
#define BT (Bsz * Tlen)      // 2048
#define C 768
#define H 12
#define HD 64
#define NL 12
#define V 50257
#define VP 50304
#define C3 (3 * C)           // 2304
#define C4 (4 * C)           // 3072
#define EPS 1e-5f

typedef __nv_bfloat16 bf16;

// ---------------- scratch ----------------
__device__ float g_x[BT * C];
__device__ float g_ln[BT * C];
__device__ float g_atty[BT * C];
__device__ float g_h[BT * C4];
__device__ float g_wpad[(long long)C * VP];
__device__ float g_wqkv[(long long)NL * C * C3];
__device__ float g_wproj[(long long)NL * C * C];
__device__ float g_wfc[(long long)NL * C * C4];
__device__ float g_wfp[(long long)NL * C4 * C];
#define QKVN (Bsz * H * Tlen * HD)
__device__ bf16 g_qh[QKVN], g_ql[QKVN];     // [bh][t][d], scaled 1/8
__device__ bf16 g_kh[QKVN], g_kl[QKVN];     // [bh][t][d]
__device__ bf16 g_vth[QKVN], g_vtl[QKVN];   // [bh][d][t]

// ---------------- helpers ----------------
__device__ __forceinline__ float gelu_f(float x) {
    float x3 = x * x * x;
    return 0.5f * x * (1.f + tanhf(0.7978845608028654f * (x + 0.044715f * x3)));
}

__device__ __forceinline__ unsigned tf32_of(float f) {
    unsigned u;
    asm("cvt.rna.tf32.f32 %0, %1;" : "=r"(u) : "f"(f));
    return u;
}
__device__ __forceinline__ float tf32r(float f) { return __uint_as_float(tf32_of(f)); }

__device__ __forceinline__ unsigned sptr(const void* p) {
    return (unsigned)__cvta_generic_to_shared(p);
}

__device__ __forceinline__ unsigned packbf(float lo, float hi) {
    unsigned r;
    asm("cvt.rn.bf16x2.f32 %0, %1, %2;" : "=r"(r) : "f"(hi), "f"(lo));
    return r;
}
__device__ __forceinline__ float lof(float x) {
    return x - __bfloat162float(__float2bfloat16(x));
}

__device__ __forceinline__ void mma_bf16(float* c, const unsigned* a, const unsigned* b) {
    asm volatile("mma.sync.aligned.m16n8k16.row.col.f32.bf16.bf16.f32 "
                 "{%0,%1,%2,%3},{%4,%5,%6,%7},{%8,%9},{%0,%1,%2,%3};"
                 : "+f"(c[0]), "+f"(c[1]), "+f"(c[2]), "+f"(c[3])
                 : "r"(a[0]), "r"(a[1]), "r"(a[2]), "r"(a[3]), "r"(b[0]), "r"(b[1]));
}
__device__ __forceinline__ void ldsm4(unsigned* r, unsigned addr) {
    asm volatile("ldmatrix.sync.aligned.m8n8.x4.shared.b16 {%0,%1,%2,%3}, [%4];"
                 : "=r"(r[0]), "=r"(r[1]), "=r"(r[2]), "=r"(r[3]) : "r"(addr));
}

// ---------------- embedding ----------------
__global__ void embed_kernel(const int* __restrict__ idx,
                             const float* __restrict__ wte,
                             const float* __restrict__ wpe,
                             float* __restrict__ out) {
    int row = blockIdx.x;
    int tpos = row % Tlen;
    int tok = idx[row];
    const float* we = wte + (long long)tok * C;
    const float* pe = wpe + (long long)tpos * C;
    float* o = out + (long long)row * C;
    for (int c = threadIdx.x; c < C; c += blockDim.x)
        o[c] = we[c] + pe[c];
}

// ---------------- weight pre-rounding ----------------
__global__ void cvtw_kernel(const float* __restrict__ w, float* __restrict__ o, long long n4) {
    long long i = (long long)blockIdx.x * blockDim.x + threadIdx.x;
    if (i < n4) {
        float4 v = ((const float4*)w)[i];
        v.x = tf32r(v.x); v.y = tf32r(v.y); v.z = tf32r(v.z); v.w = tf32r(v.w);
        ((float4*)o)[i] = v;
    }
}

// ---------------- lm_head pad + round ----------------
__global__ void padw_kernel(const float* __restrict__ w, float* __restrict__ wp) {
    int k = blockIdx.y;
    int n = blockIdx.x * blockDim.x + threadIdx.x;
    if (n < VP)
        wp[(long long)k * VP + n] = (n < V) ? tf32r(w[(long long)k * V + n]) : 0.f;
}

// ---------------- layernorm (tf32-rounded output) ----------------
__global__ void ln_kernel(const float* __restrict__ x,
                          const float* __restrict__ w,
                          const float* __restrict__ b,
                          float* __restrict__ out) {
    __shared__ float red[256];
    __shared__ float red2[256];
    int row = blockIdx.x;
    const float* xr = x + (long long)row * C;
    float s = 0.f, sq = 0.f;
    for (int c = threadIdx.x; c < C; c += blockDim.x) {
        float v = xr[c];
        s += v; sq += v * v;
    }
    red[threadIdx.x] = s; red2[threadIdx.x] = sq;
    __syncthreads();
    for (int off = 128; off > 0; off >>= 1) {
        if (threadIdx.x < off) {
            red[threadIdx.x] += red[threadIdx.x + off];
            red2[threadIdx.x] += red2[threadIdx.x + off];
        }
        __syncthreads();
    }
    float mean = red[0] / C;
    float var = red2[0] / C - mean * mean;
    float rstd = rsqrtf(var + EPS);
    float* o = out + (long long)row * C;
    for (int c = threadIdx.x; c < C; c += blockDim.x)
        o[c] = tf32r((xr[c] - mean) * rstd * w[c] + b[c]);
}

// ---------------- 3-stage cp.async tf32 GEMM ----------------
// epi: 0=+bias, 1=gelu->round, 2=+bias+residual, 3=none, 4=qkv split
#define ASTR 20
#define BSTR 136

template<int BM>
__global__ void __launch_bounds__(256, 2)
tgemm_kernel(const float* __restrict__ A, const float* __restrict__ W,
             const float* __restrict__ bias, float* __restrict__ out,
             int M, int N, int K, int ldw, int epi,
             bf16* qh, bf16* ql, bf16* kh, bf16* kl, bf16* vth, bf16* vtl) {
    constexpr int MI = BM / 32;
    extern __shared__ float sm[];
    float* As = sm;
    float* Bs = sm + 3 * BM * ASTR;

    int tid = threadIdx.x;
    int w = tid >> 5, lane = tid & 31;
    int g = lane >> 2, tig = lane & 3;
    int wm = (w & 1) * (BM / 2);
    int wn = (w >> 1) * 32;
    int m0 = blockIdx.y * BM;
    int n0 = blockIdx.x * 128;

    float acc[MI][4][4];
#pragma unroll
    for (int mi = 0; mi < MI; mi++)
#pragma unroll
        for (int nj = 0; nj < 4; nj++)
#pragma unroll
            for (int r = 0; r < 4; r++) acc[mi][nj][r] = 0.f;

    auto loadTiles = [&](int kt, int s) {
        int k0 = kt * 16;
        float* as = As + s * (BM * ASTR);
        float* bs = Bs + s * (16 * BSTR);
#pragma unroll
        for (int i = 0; i < BM / 64; i++) {
            int id = tid + i * 256;
            int row = id >> 2, kc = (id & 3) * 4;
            unsigned dst = sptr(&as[row * ASTR + kc]);
            const float* src = A + (long long)(m0 + row) * K + k0 + kc;
            asm volatile("cp.async.cg.shared.global [%0], [%1], 16;" :: "r"(dst), "l"(src));
        }
#pragma unroll
        for (int i = 0; i < 2; i++) {
            int id = tid + i * 256;
            int row = id >> 5, nc = (id & 31) * 4;
            unsigned dst = sptr(&bs[row * BSTR + nc]);
            const float* src = W + (long long)(k0 + row) * ldw + n0 + nc;
            asm volatile("cp.async.cg.shared.global [%0], [%1], 16;" :: "r"(dst), "l"(src));
        }
    };

    int nk = K / 16;
    loadTiles(0, 0);
    asm volatile("cp.async.commit_group;");
    loadTiles(1, 1);
    asm volatile("cp.async.commit_group;");

    for (int kt = 0; kt < nk; kt++) {
        asm volatile("cp.async.wait_group 1;");
        __syncthreads();

        if (kt + 2 < nk) loadTiles(kt + 2, (kt + 2) % 3);
        asm volatile("cp.async.commit_group;");

        int cur = kt % 3;
        const float* as = As + cur * (BM * ASTR);
        const float* bs = Bs + cur * (16 * BSTR);

#pragma unroll
        for (int kk = 0; kk < 2; kk++) {
            unsigned af[MI][4], bf[4][2];
#pragma unroll
            for (int mi = 0; mi < MI; mi++) {
                int r = wm + mi * 16 + g;
                af[mi][0] = __float_as_uint(as[r * ASTR + kk * 8 + tig]);
                af[mi][1] = __float_as_uint(as[(r + 8) * ASTR + kk * 8 + tig]);
                af[mi][2] = __float_as_uint(as[r * ASTR + kk * 8 + tig + 4]);
                af[mi][3] = __float_as_uint(as[(r + 8) * ASTR + kk * 8 + tig + 4]);
            }
#pragma unroll
            for (int nj = 0; nj < 4; nj++) {
                int col = wn + nj * 8 + g;
                bf[nj][0] = __float_as_uint(bs[(kk * 8 + tig) * BSTR + col]);
                bf[nj][1] = __float_as_uint(bs[(kk * 8 + tig + 4) * BSTR + col]);
            }
#pragma unroll
            for (int mi = 0; mi < MI; mi++)
#pragma unroll
                for (int nj = 0; nj < 4; nj++)
                    asm volatile(
                        "mma.sync.aligned.m16n8k8.row.col.f32.tf32.tf32.f32 "
                        "{%0,%1,%2,%3},{%4,%5,%6,%7},{%8,%9},{%0,%1,%2,%3};\n"
                        : "+f"(acc[mi][nj][0]), "+f"(acc[mi][nj][1]),
                          "+f"(acc[mi][nj][2]), "+f"(acc[mi][nj][3])
                        : "r"(af[mi][0]), "r"(af[mi][1]), "r"(af[mi][2]), "r"(af[mi][3]),
                          "r"(bf[nj][0]), "r"(bf[nj][1]));
        }
    }

#pragma unroll
    for (int mi = 0; mi < MI; mi++) {
        int r0 = m0 + wm + mi * 16 + g;
#pragma unroll
        for (int nj = 0; nj < 4; nj++) {
            int col = n0 + wn + nj * 8 + 2 * tig;
#pragma unroll
            for (int half = 0; half < 2; half++) {
                int rr = r0 + half * 8;
#pragma unroll
                for (int jj = 0; jj < 2; jj++) {
                    int cc = col + jj;
                    if (cc < N) {
                        float v = acc[mi][nj][half * 2 + jj];
                        if (epi != 3) v += bias[cc];
                        if (epi == 4) {
                            int t = rr & (Tlen - 1);
                            int bb = rr >> 10;
                            int sec = cc / C;
                            int wi = cc - sec * C;
                            long long bh = (long long)(bb * H + (wi >> 6));
                            int d = wi & 63;
                            if (sec == 0) {
                                float q = v * 0.125f;
                                long long o2 = (bh * Tlen + t) * HD + d;
                                qh[o2] = __float2bfloat16(q);
                                ql[o2] = __float2bfloat16(lof(q));
                            } else if (sec == 1) {
                                long long o2 = (bh * Tlen + t) * HD + d;
                                kh[o2] = __float2bfloat16(v);
                                kl[o2] = __float2bfloat16(lof(v));
                            } else {
                                long long o2 = (bh * HD + d) * Tlen + t;
                                vth[o2] = __float2bfloat16(v);
                                vtl[o2] = __float2bfloat16(lof(v));
                            }
                        } else {
                            if (epi == 1) v = tf32r(gelu_f(v));
                            long long o = (long long)rr * N + cc;
                            if (epi == 2) v += out[o];
                            out[o] = v;
                        }
                    }
                }
            }
        }
    }
}

// ---------------- tensor-core flash attention (double-buffered cp.async) ----------------
// Block: 64 q x 1 head, 128 threads (4 warps). kv tiles of 64, 2-stage pipeline.
// Stage layout: [Kh | Kl | Vh | Vl], each 64*FAST bf16.
#define FAST 72
#define FTILE (64 * FAST)   // elems per array

__global__ void __launch_bounds__(128)
fattn_kernel(const bf16* __restrict__ qh, const bf16* __restrict__ ql,
             const bf16* __restrict__ kh, const bf16* __restrict__ kl,
             const bf16* __restrict__ vth, const bf16* __restrict__ vtl,
             float* __restrict__ out) {
    extern __shared__ __align__(16) bf16 smb[];
    bf16* sQh = smb;
    bf16* sQl = smb + FTILE;
    bf16* sT  = smb + 2 * FTILE;   // stage s at sT + s*4*FTILE

    int tid = threadIdx.x;
    int w = tid >> 5, lane = tid & 31;
    int g = lane >> 2, tig = lane & 3;
    int qt = (int)gridDim.x - 1 - (int)blockIdx.x;  // heavy tiles first
    int h = blockIdx.y, b = blockIdx.z;
    int q0 = qt * 64;
    long long bh = (long long)(b * H + h);
    int ntiles = qt + 1;

    // per-thread loader mapping (2 row-jobs over 4 arrays x 64 rows)
    int jrow0 = tid & 63, jsel0 = tid >> 6;          // jobs 0..127
    int jrow1 = jrow0, jsel1 = jsel0 + 2;            // jobs 128..255

    auto loadTile = [&](int kt2, int st) {
        int kv0 = kt2 * 64;
        bf16* base = sT + st * (4 * FTILE);
        {
            const bf16* src = (jsel0 == 0) ? kh + (bh * Tlen + kv0 + jrow0) * HD
                                           : kl + (bh * Tlen + kv0 + jrow0) * HD;
            bf16* db = base + jsel0 * FTILE;
            unsigned dst = sptr(db) + (unsigned)(jrow0 * FAST) * 2u;
#pragma unroll
            for (int j = 0; j < 8; j++)
                asm volatile("cp.async.cg.shared.global [%0], [%1], 16;"
                             :: "r"(dst + j * 16), "l"(src + j * 8));
        }
        {
            const bf16* src = (jsel1 == 2) ? vth + (bh * HD + jrow1) * Tlen + kv0
                                           : vtl + (bh * HD + jrow1) * Tlen + kv0;
            bf16* db = base + jsel1 * FTILE;
            unsigned dst = sptr(db) + (unsigned)(jrow1 * FAST) * 2u;
#pragma unroll
            for (int j = 0; j < 8; j++)
                asm volatile("cp.async.cg.shared.global [%0], [%1], 16;"
                             :: "r"(dst + j * 16), "l"(src + j * 8));
        }
    };

    // ---- prologue: Q loads (group 1) + tile 0 (group 2), overlapped ----
    {
        int row = tid & 63;
        const bf16* src = ((tid >> 6) ? ql : qh) + (bh * Tlen + q0 + row) * HD;
        bf16* db = (tid >> 6) ? sQl : sQh;
        unsigned dst = sptr(db) + (unsigned)(row * FAST) * 2u;
#pragma unroll
        for (int j = 0; j < 8; j++)
            asm volatile("cp.async.cg.shared.global [%0], [%1], 16;"
                         :: "r"(dst + j * 16), "l"(src + j * 8));
    }
    asm volatile("cp.async.commit_group;");
    loadTile(0, 0);
    asm volatile("cp.async.commit_group;");

    asm volatile("cp.async.wait_group 1;");   // Q ready; tile 0 still in flight
    __syncthreads();

    // ---- Q fragments ----
    unsigned aQh[4][4], aQl[4][4];
    {
        int arow = w * 16 + (lane & 15);
        int acol8 = (lane >> 4) << 3;
        unsigned qaH = sptr(sQh) + (unsigned)(arow * FAST + acol8) * 2;
        unsigned qaL = sptr(sQl) + (unsigned)(arow * FAST + acol8) * 2;
#pragma unroll
        for (int kk = 0; kk < 4; kk++) {
            ldsm4(aQh[kk], qaH + kk * 32);
            ldsm4(aQl[kk], qaL + kk * 32);
        }
    }

    int brow_off = (lane & 7) + ((lane & 16) ? 8 : 0);
    int bcol_off = (lane & 8) ? 8 : 0;
    unsigned bofs = (unsigned)(brow_off * FAST + bcol_off) * 2;
    unsigned kbH0 = sptr(sT) + bofs;
    unsigned kbL0 = kbH0 + FTILE * 2;
    unsigned vbH0 = kbH0 + 2 * FTILE * 2;
    unsigned vbL0 = kbH0 + 3 * FTILE * 2;
    const unsigned PSTEP = 16u * FAST * 2u;
    const unsigned SSTEP = 4u * FTILE * 2u;   // stage stride (bytes)

    float of[8][4];
#pragma unroll
    for (int nj = 0; nj < 8; nj++)
#pragma unroll
        for (int r = 0; r < 4; r++) of[nj][r] = 0.f;
    float ls0 = 0.f, ls1 = 0.f;

    int qg0 = q0 + w * 16 + g;
    int qg1 = qg0 + 8;

    for (int kt = 0; kt < ntiles; kt++) {
        int s = kt & 1;
        int kv0 = kt * 64;

        asm volatile("cp.async.wait_group 0;");   // tile kt ready
        __syncthreads();

        // prefetch next tile into the other stage (clamped on last iter)
        int ktn = (kt + 1 < ntiles) ? kt + 1 : kt;
        loadTile(ktn, s ^ 1);
        asm volatile("cp.async.commit_group;");

        unsigned so = (unsigned)s * SSTEP;
        unsigned kbH = kbH0 + so, kbL = kbL0 + so;
        unsigned vbH = vbH0 + so, vbL = vbL0 + so;

        // ---- S = Q @ K^T (3-term) ----
        float c[8][4];
#pragma unroll
        for (int nj = 0; nj < 8; nj++)
#pragma unroll
            for (int r = 0; r < 4; r++) c[nj][r] = 0.f;

#pragma unroll
        for (int kk = 0; kk < 4; kk++) {
            unsigned bhf[8][2], blf[8][2], t[4];
#pragma unroll
            for (int p = 0; p < 4; p++) {
                ldsm4(t, kbH + p * PSTEP + kk * 32);
                bhf[2 * p][0] = t[0]; bhf[2 * p][1] = t[1];
                bhf[2 * p + 1][0] = t[2]; bhf[2 * p + 1][1] = t[3];
                ldsm4(t, kbL + p * PSTEP + kk * 32);
                blf[2 * p][0] = t[0]; blf[2 * p][1] = t[1];
                blf[2 * p + 1][0] = t[2]; blf[2 * p + 1][1] = t[3];
            }
#pragma unroll
            for (int nj = 0; nj < 8; nj++) {
                mma_bf16(c[nj], aQh[kk], bhf[nj]);
                mma_bf16(c[nj], aQh[kk], blf[nj]);
                mma_bf16(c[nj], aQl[kk], bhf[nj]);
            }
        }

        // ---- fixed-shift softmax on fragments ----
        bool diag = (kt == qt);
#pragma unroll
        for (int nj = 0; nj < 8; nj++) {
            int colb = kv0 + 8 * nj + 2 * tig;
            float p0 = __expf(c[nj][0]);
            float p1 = __expf(c[nj][1]);
            float p2 = __expf(c[nj][2]);
            float p3 = __expf(c[nj][3]);
            if (diag) {
                if (colb > qg0)     p0 = 0.f;
                if (colb + 1 > qg0) p1 = 0.f;
                if (colb > qg1)     p2 = 0.f;
                if (colb + 1 > qg1) p3 = 0.f;
            }
            c[nj][0] = p0; c[nj][1] = p1; c[nj][2] = p2; c[nj][3] = p3;
            ls0 += p0 + p1;
            ls1 += p2 + p3;
        }

        // ---- O += P @ V (3-term) ----
#pragma unroll
        for (int kk = 0; kk < 4; kk++) {
            unsigned aph[4], apl[4];
            aph[0] = packbf(c[2 * kk][0], c[2 * kk][1]);
            aph[1] = packbf(c[2 * kk][2], c[2 * kk][3]);
            aph[2] = packbf(c[2 * kk + 1][0], c[2 * kk + 1][1]);
            aph[3] = packbf(c[2 * kk + 1][2], c[2 * kk + 1][3]);
            apl[0] = packbf(lof(c[2 * kk][0]), lof(c[2 * kk][1]));
            apl[1] = packbf(lof(c[2 * kk][2]), lof(c[2 * kk][3]));
            apl[2] = packbf(lof(c[2 * kk + 1][0]), lof(c[2 * kk + 1][1]));
            apl[3] = packbf(lof(c[2 * kk + 1][2]), lof(c[2 * kk + 1][3]));

            unsigned vh[8][2], vl[8][2], t[4];
#pragma unroll
            for (int p = 0; p < 4; p++) {
                ldsm4(t, vbH + p * PSTEP + kk * 32);
                vh[2 * p][0] = t[0]; vh[2 * p][1] = t[1];
                vh[2 * p + 1][0] = t[2]; vh[2 * p + 1][1] = t[3];
                ldsm4(t, vbL + p * PSTEP + kk * 32);
                vl[2 * p][0] = t[0]; vl[2 * p][1] = t[1];
                vl[2 * p + 1][0] = t[2]; vl[2 * p + 1][1] = t[3];
            }
#pragma unroll
            for (int nj = 0; nj < 8; nj++) {
                mma_bf16(of[nj], aph, vh[nj]);
                mma_bf16(of[nj], apl, vh[nj]);
                mma_bf16(of[nj], aph, vl[nj]);
            }
        }
    }

    // ---- l reduction ----
    ls0 += __shfl_xor_sync(0xFFFFFFFFu, ls0, 1);
    ls0 += __shfl_xor_sync(0xFFFFFFFFu, ls0, 2);
    ls1 += __shfl_xor_sync(0xFFFFFFFFu, ls1, 1);
    ls1 += __shfl_xor_sync(0xFFFFFFFFu, ls1, 2);
    float inv0 = 1.f / ls0;
    float inv1 = 1.f / ls1;

    long long r0 = (long long)(b * Tlen + qg0) * C + h * HD;
    long long r1 = (long long)(b * Tlen + qg1) * C + h * HD;
#pragma unroll
    for (int nj = 0; nj < 8; nj++) {
        int col = 8 * nj + 2 * tig;
        float2 v0, v1;
        v0.x = tf32r(of[nj][0] * inv0); v0.y = tf32r(of[nj][1] * inv0);
        v1.x = tf32r(of[nj][2] * inv1); v1.y = tf32r(of[nj][3] * inv1);
        *(float2*)&out[r0 + col] = v0;
        *(float2*)&out[r1 + col] = v1;
    }
}

// ---------------- driver ----------------
#define GEMM_SMEM(BM) (3 * ((BM) * ASTR + 16 * BSTR) * (int)sizeof(float))
#define ATTN_SMEM ((2 + 8) * FTILE * (int)sizeof(bf16))

extern "C" void kernel_launch(void* const* d_in, const int* in_sizes, int n_in,
                              void* d_out, int out_size) {
    const int*   idx      = (const int*)  d_in[0];
    const float* wte      = (const float*)d_in[1];
    const float* wpe      = (const float*)d_in[2];
    const float* ln1_w    = (const float*)d_in[3];
    const float* ln1_b    = (const float*)d_in[4];
    const float* attn_w   = (const float*)d_in[5];
    const float* attn_b   = (const float*)d_in[6];
    const float* proj_w   = (const float*)d_in[7];
    const float* proj_b   = (const float*)d_in[8];
    const float* ln2_w    = (const float*)d_in[9];
    const float* ln2_b    = (const float*)d_in[10];
    const float* fc_w     = (const float*)d_in[11];
    const float* fc_b     = (const float*)d_in[12];
    const float* fcproj_w = (const float*)d_in[13];
    const float* fcproj_b = (const float*)d_in[14];
    const float* lnf_w    = (const float*)d_in[15];
    const float* lnf_b    = (const float*)d_in[16];
    const float* lm_head  = (const float*)d_in[17];
    float* out = (float*)d_out;

    float *x, *ln, *atty, *hbuf, *wpad, *wq, *wp, *wf, *wfp;
    bf16 *qh, *ql, *kh, *kl, *vth, *vtl;
    cudaGetSymbolAddress((void**)&x,    g_x);
    cudaGetSymbolAddress((void**)&ln,   g_ln);
    cudaGetSymbolAddress((void**)&atty, g_atty);
    cudaGetSymbolAddress((void**)&hbuf, g_h);
    cudaGetSymbolAddress((void**)&wpad, g_wpad);
    cudaGetSymbolAddress((void**)&wq,   g_wqkv);
    cudaGetSymbolAddress((void**)&wp,   g_wproj);
    cudaGetSymbolAddress((void**)&wf,   g_wfc);
    cudaGetSymbolAddress((void**)&wfp,  g_wfp);
    cudaGetSymbolAddress((void**)&qh,   g_qh);
    cudaGetSymbolAddress((void**)&ql,   g_ql);
    cudaGetSymbolAddress((void**)&kh,   g_kh);
    cudaGetSymbolAddress((void**)&kl,   g_kl);
    cudaGetSymbolAddress((void**)&vth,  g_vth);
    cudaGetSymbolAddress((void**)&vtl,  g_vtl);

    cudaFuncSetAttribute(tgemm_kernel<128>,
                         cudaFuncAttributeMaxDynamicSharedMemorySize, GEMM_SMEM(128));
    cudaFuncSetAttribute(tgemm_kernel<64>,
                         cudaFuncAttributeMaxDynamicSharedMemorySize, GEMM_SMEM(64));
    cudaFuncSetAttribute(fattn_kernel,
                         cudaFuncAttributeMaxDynamicSharedMemorySize, ATTN_SMEM);

    {
        long long n4;
        n4 = (long long)NL * C * C3 / 4;
        cvtw_kernel<<<(int)((n4 + 255) / 256), 256>>>(attn_w, wq, n4);
        n4 = (long long)NL * C * C / 4;
        cvtw_kernel<<<(int)((n4 + 255) / 256), 256>>>(proj_w, wp, n4);
        n4 = (long long)NL * C * C4 / 4;
        cvtw_kernel<<<(int)((n4 + 255) / 256), 256>>>(fc_w, wf, n4);
        n4 = (long long)NL * C4 * C / 4;
        cvtw_kernel<<<(int)((n4 + 255) / 256), 256>>>(fcproj_w, wfp, n4);
    }
    padw_kernel<<<dim3((VP + 255) / 256, C), 256>>>(lm_head, wpad);
    embed_kernel<<<BT, 256>>>(idx, wte, wpe, x);

    for (int l = 0; l < NL; l++) {
        ln_kernel<<<BT, 256>>>(x, ln1_w + l * C, ln1_b + l * C, ln);
        tgemm_kernel<128><<<dim3(C3 / 128, BT / 128), 256, GEMM_SMEM(128)>>>(
            ln, wq + (long long)l * C * C3, attn_b + l * C3, nullptr, BT, C3, C, C3, 4,
            qh, ql, kh, kl, vth, vtl);
        fattn_kernel<<<dim3(Tlen / 64, H, Bsz), 128, ATTN_SMEM>>>(
            qh, ql, kh, kl, vth, vtl, atty);
        tgemm_kernel<64><<<dim3(C / 128, BT / 64), 256, GEMM_SMEM(64)>>>(
            atty, wp + (long long)l * C * C, proj_b + l * C, x, BT, C, C, C, 2,
            nullptr, nullptr, nullptr, nullptr, nullptr, nullptr);
        ln_kernel<<<BT, 256>>>(x, ln2_w + l * C, ln2_b + l * C, ln);
        tgemm_kernel<128><<<dim3(C4 / 128, BT / 128), 256, GEMM_SMEM(128)>>>(
            ln, wf + (long long)l * C * C4, fc_b + l * C4, hbuf, BT, C4, C, C4, 1,
            nullptr, nullptr, nullptr, nullptr, nullptr, nullptr);
        tgemm_kernel<64><<<dim3(C / 128, BT / 64), 256, GEMM_SMEM(64)>>>(
            hbuf, wfp + (long long)l * C4 * C, fcproj_b + l * C, x, BT, C, C4, C, 2,
            nullptr, nullptr, nullptr, nullptr, nullptr, nullptr);
    }

    ln_kernel<<<BT, 256>>>(x, lnf_w, lnf_b, ln);
    tgemm_kernel<128><<<dim3(VP / 128, BT / 128), 256, GEMM_SMEM(128)>>>(
        ln, wpad, (const float*)nullptr, out, BT, V, C, VP, 3,
        nullptr, nullptr, nullptr, nullptr, nullptr, nullptr);
}

// round 17
// speedup vs baseline: 1.5611x; 1.5502x over previous
#include <cuda_runtime.h>
#include <cuda_bf16.h>
#include <cuda_fp16.h>
#include <math.h>

// GPT-2 small forward: fp16 mma.sync m16n8k16 GEMMs (weights pre-transposed [N,K] fp16)
// + bf16-split tensor-core flash attention (double-buffered cp.async).
// B=2, T=1024, C=768, H=12, HD=64, L=12, V=50257.

#define Bsz 2
#define Tlen 1024
#define BT (Bsz * Tlen)      // 2048
#define C 768
#define H 12
#define HD 64
#define NL 12
#define V 50257
#define VP 50304
#define C3 (3 * C)           // 2304
#define C4 (4 * C)           // 3072
#define EPS 1e-5f

typedef __nv_bfloat16 bf16;

// ---------------- scratch ----------------
__device__ float g_x[BT * C];               // residual (fp32)
__device__ __half g_ln[BT * C];             // LN output (fp16)
__device__ __half g_atty[BT * C];           // attention output (fp16)
__device__ __half g_h[BT * C4];             // gelu output (fp16)
// transposed fp16 weights [N][K]
__device__ __half g_wqkv[(long long)NL * C3 * C];
__device__ __half g_wproj[(long long)NL * C * C];
__device__ __half g_wfc[(long long)NL * C4 * C];
__device__ __half g_wfp[(long long)NL * C * C4];
__device__ __half g_wlm[(long long)VP * C];
#define QKVN (Bsz * H * Tlen * HD)
__device__ bf16 g_qh[QKVN], g_ql[QKVN];     // [bh][t][d], scaled 1/8
__device__ bf16 g_kh[QKVN], g_kl[QKVN];     // [bh][t][d]
__device__ bf16 g_vth[QKVN], g_vtl[QKVN];   // [bh][d][t]

// ---------------- helpers ----------------
__device__ __forceinline__ float gelu_f(float x) {
    float x3 = x * x * x;
    return 0.5f * x * (1.f + tanhf(0.7978845608028654f * (x + 0.044715f * x3)));
}

__device__ __forceinline__ unsigned sptr(const void* p) {
    return (unsigned)__cvta_generic_to_shared(p);
}

__device__ __forceinline__ unsigned packbf(float lo, float hi) {
    unsigned r;
    asm("cvt.rn.bf16x2.f32 %0, %1, %2;" : "=r"(r) : "f"(hi), "f"(lo));
    return r;
}
__device__ __forceinline__ float lof(float x) {
    return x - __bfloat162float(__float2bfloat16(x));
}

__device__ __forceinline__ void mma_bf16(float* c, const unsigned* a, const unsigned* b) {
    asm volatile("mma.sync.aligned.m16n8k16.row.col.f32.bf16.bf16.f32 "
                 "{%0,%1,%2,%3},{%4,%5,%6,%7},{%8,%9},{%0,%1,%2,%3};"
                 : "+f"(c[0]), "+f"(c[1]), "+f"(c[2]), "+f"(c[3])
                 : "r"(a[0]), "r"(a[1]), "r"(a[2]), "r"(a[3]), "r"(b[0]), "r"(b[1]));
}
__device__ __forceinline__ void mma_fp16(float* c, const unsigned* a, const unsigned* b) {
    asm volatile("mma.sync.aligned.m16n8k16.row.col.f32.f16.f16.f32 "
                 "{%0,%1,%2,%3},{%4,%5,%6,%7},{%8,%9},{%0,%1,%2,%3};"
                 : "+f"(c[0]), "+f"(c[1]), "+f"(c[2]), "+f"(c[3])
                 : "r"(a[0]), "r"(a[1]), "r"(a[2]), "r"(a[3]), "r"(b[0]), "r"(b[1]));
}
__device__ __forceinline__ void ldsm4(unsigned* r, unsigned addr) {
    asm volatile("ldmatrix.sync.aligned.m8n8.x4.shared.b16 {%0,%1,%2,%3}, [%4];"
                 : "=r"(r[0]), "=r"(r[1]), "=r"(r[2]), "=r"(r[3]) : "r"(addr));
}

// ---------------- embedding ----------------
__global__ void embed_kernel(const int* __restrict__ idx,
                             const float* __restrict__ wte,
                             const float* __restrict__ wpe,
                             float* __restrict__ out) {
    int row = blockIdx.x;
    int tpos = row % Tlen;
    int tok = idx[row];
    const float* we = wte + (long long)tok * C;
    const float* pe = wpe + (long long)tpos * C;
    float* o = out + (long long)row * C;
    for (int c = threadIdx.x; c < C; c += blockDim.x)
        o[c] = we[c] + pe[c];
}

// ---------------- weight transpose + fp16: W[K,N] -> Wt[Nout,K] ----------------
// grid (Nout/32, K/32, L), block (32, 8). Reads guarded by n<N (zero-pad rows beyond).
__global__ void transw_kernel(const float* __restrict__ w, __half* __restrict__ wt,
                              int K, int N, long long inL, long long outL) {
    __shared__ float t[32][33];
    int l = blockIdx.z;
    int k0 = blockIdx.y * 32, n0 = blockIdx.x * 32;
    int tx = threadIdx.x, ty = threadIdx.y;
    const float* wp = w + l * inL;
#pragma unroll
    for (int i = 0; i < 4; i++) {
        int n = n0 + tx;
        t[ty + i * 8][tx] = (n < N) ? wp[(long long)(k0 + ty + i * 8) * N + n] : 0.f;
    }
    __syncthreads();
#pragma unroll
    for (int i = 0; i < 4; i++) {
        int n = n0 + ty + i * 8;
        wt[l * outL + (long long)n * K + k0 + tx] = __float2half(t[tx][ty + i * 8]);
    }
}

// ---------------- layernorm (fp16 output) ----------------
__global__ void ln_kernel(const float* __restrict__ x,
                          const float* __restrict__ w,
                          const float* __restrict__ b,
                          __half* __restrict__ out) {
    __shared__ float red[256];
    __shared__ float red2[256];
    int row = blockIdx.x;
    const float* xr = x + (long long)row * C;
    float s = 0.f, sq = 0.f;
    for (int c = threadIdx.x; c < C; c += blockDim.x) {
        float v = xr[c];
        s += v; sq += v * v;
    }
    red[threadIdx.x] = s; red2[threadIdx.x] = sq;
    __syncthreads();
    for (int off = 128; off > 0; off >>= 1) {
        if (threadIdx.x < off) {
            red[threadIdx.x] += red[threadIdx.x + off];
            red2[threadIdx.x] += red2[threadIdx.x + off];
        }
        __syncthreads();
    }
    float mean = red[0] / C;
    float var = red2[0] / C - mean * mean;
    float rstd = rsqrtf(var + EPS);
    __half* o = out + (long long)row * C;
    for (int c = threadIdx.x; c < C; c += blockDim.x)
        o[c] = __float2half((xr[c] - mean) * rstd * w[c] + b[c]);
}

// ---------------- fp16 mma.sync GEMM (A [M,K] fp16, Wt [N,K] fp16) ----------------
// epi: 1=gelu->fp16, 2=+bias+residual(fp32), 3=none(fp32 out, col guard), 4=qkv split
// 256 threads / 8 warps (2m x 4n), tile BM x 128, warp tile (BM/2) x 32, K-tile 32, 3 stages.
#define HST 40   // fp16 row stride (80B): ldmatrix conflict-free, 16B-aligned rows

template<int BM>
__global__ void __launch_bounds__(256, 2)
hgemm_kernel(const __half* __restrict__ A, const __half* __restrict__ Wt,
             const float* __restrict__ bias, float* __restrict__ out,
             __half* __restrict__ outh,
             int M, int N, int K, int epi,
             bf16* qh, bf16* ql, bf16* kh, bf16* kl, bf16* vth, bf16* vtl) {
    constexpr int MI = BM / 32;
    extern __shared__ __half hsm[];
    __half* As = hsm;                        // 3 stages of BM*HST
    __half* Bs = hsm + 3 * BM * HST;         // 3 stages of 128*HST

    int tid = threadIdx.x;
    int w = tid >> 5, lane = tid & 31;
    int g = lane >> 2, tig = lane & 3;
    int wm = (w & 1) * (BM / 2);
    int wn = (w >> 1) * 32;
    int m0 = blockIdx.y * BM;
    int n0 = blockIdx.x * 128;

    float acc[MI][4][4];
#pragma unroll
    for (int mi = 0; mi < MI; mi++)
#pragma unroll
        for (int nj = 0; nj < 4; nj++)
#pragma unroll
            for (int r = 0; r < 4; r++) acc[mi][nj][r] = 0.f;

    auto loadTiles = [&](int kt, int s) {
        int k0 = kt * 32;
        __half* as = As + s * (BM * HST);
        __half* bs = Bs + s * (128 * HST);
        // A: BM rows x 32 k (64B/row = 4 chunks); BM*4/256 iters
#pragma unroll
        for (int i = 0; i < BM / 64; i++) {
            int id = tid + i * 256;
            int row = id >> 2, kc = (id & 3) * 8;
            unsigned dst = sptr(&as[row * HST + kc]);
            const __half* src = A + (long long)(m0 + row) * K + k0 + kc;
            asm volatile("cp.async.cg.shared.global [%0], [%1], 16;" :: "r"(dst), "l"(src));
        }
        // B: 128 rows x 32 k
#pragma unroll
        for (int i = 0; i < 2; i++) {
            int id = tid + i * 256;
            int row = id >> 2, kc = (id & 3) * 8;
            unsigned dst = sptr(&bs[row * HST + kc]);
            const __half* src = Wt + (long long)(n0 + row) * K + k0 + kc;
            asm volatile("cp.async.cg.shared.global [%0], [%1], 16;" :: "r"(dst), "l"(src));
        }
    };

    int nk = K / 32;
    loadTiles(0, 0);
    asm volatile("cp.async.commit_group;");
    loadTiles(1, 1);
    asm volatile("cp.async.commit_group;");

    // fragment lane offsets (validated pattern from attention kernel)
    int arow_off = lane & 15;
    int acol_off = (lane >> 4) << 3;
    int brow_off = (lane & 7) + ((lane & 16) ? 8 : 0);
    int bcol_off = (lane & 8) ? 8 : 0;

    for (int kt = 0; kt < nk; kt++) {
        asm volatile("cp.async.wait_group 1;");
        __syncthreads();

        if (kt + 2 < nk) loadTiles(kt + 2, (kt + 2) % 3);
        asm volatile("cp.async.commit_group;");

        int cur = kt % 3;
        const __half* as = As + cur * (BM * HST);
        const __half* bs = Bs + cur * (128 * HST);

#pragma unroll
        for (int kk = 0; kk < 2; kk++) {
            unsigned aF[MI][4], bF[4][2];
#pragma unroll
            for (int mi = 0; mi < MI; mi++) {
                unsigned addr = sptr(as) +
                    (unsigned)((wm + mi * 16 + arow_off) * HST + kk * 16 + acol_off) * 2;
                ldsm4(aF[mi], addr);
            }
#pragma unroll
            for (int p = 0; p < 2; p++) {
                unsigned t[4];
                unsigned addr = sptr(bs) +
                    (unsigned)((wn + p * 16 + brow_off) * HST + kk * 16 + bcol_off) * 2;
                ldsm4(t, addr);
                bF[2 * p][0] = t[0]; bF[2 * p][1] = t[1];
                bF[2 * p + 1][0] = t[2]; bF[2 * p + 1][1] = t[3];
            }
#pragma unroll
            for (int mi = 0; mi < MI; mi++)
#pragma unroll
                for (int nj = 0; nj < 4; nj++)
                    mma_fp16(acc[mi][nj], aF[mi], bF[nj]);
        }
    }

    // ---- epilogue ----
#pragma unroll
    for (int mi = 0; mi < MI; mi++) {
        int r0 = m0 + wm + mi * 16 + g;
#pragma unroll
        for (int nj = 0; nj < 4; nj++) {
            int col = n0 + wn + nj * 8 + 2 * tig;
#pragma unroll
            for (int half = 0; half < 2; half++) {
                int rr = r0 + half * 8;
#pragma unroll
                for (int jj = 0; jj < 2; jj++) {
                    int cc = col + jj;
                    if (cc < N) {
                        float v = acc[mi][nj][half * 2 + jj];
                        if (epi != 3) v += bias[cc];
                        if (epi == 4) {
                            int t = rr & (Tlen - 1);
                            int bb = rr >> 10;
                            int sec = cc / C;
                            int wi = cc - sec * C;
                            long long bh = (long long)(bb * H + (wi >> 6));
                            int d = wi & 63;
                            if (sec == 0) {
                                float q = v * 0.125f;
                                long long o2 = (bh * Tlen + t) * HD + d;
                                qh[o2] = __float2bfloat16(q);
                                ql[o2] = __float2bfloat16(lof(q));
                            } else if (sec == 1) {
                                long long o2 = (bh * Tlen + t) * HD + d;
                                kh[o2] = __float2bfloat16(v);
                                kl[o2] = __float2bfloat16(lof(v));
                            } else {
                                long long o2 = (bh * HD + d) * Tlen + t;
                                vth[o2] = __float2bfloat16(v);
                                vtl[o2] = __float2bfloat16(lof(v));
                            }
                        } else if (epi == 1) {
                            outh[(long long)rr * N + cc] = __float2half(gelu_f(v));
                        } else {
                            long long o = (long long)rr * N + cc;
                            if (epi == 2) v += out[o];
                            out[o] = v;
                        }
                    }
                }
            }
        }
    }
}

// ---------------- tensor-core flash attention (R16, fp16 output) ----------------
#define FAST 72
#define FTILE (64 * FAST)

__global__ void __launch_bounds__(128)
fattn_kernel(const bf16* __restrict__ qh, const bf16* __restrict__ ql,
             const bf16* __restrict__ kh, const bf16* __restrict__ kl,
             const bf16* __restrict__ vth, const bf16* __restrict__ vtl,
             __half* __restrict__ out) {
    extern __shared__ __align__(16) bf16 smb[];
    bf16* sQh = smb;
    bf16* sQl = smb + FTILE;
    bf16* sT  = smb + 2 * FTILE;

    int tid = threadIdx.x;
    int w = tid >> 5, lane = tid & 31;
    int g = lane >> 2, tig = lane & 3;
    int qt = (int)gridDim.x - 1 - (int)blockIdx.x;
    int h = blockIdx.y, b = blockIdx.z;
    int q0 = qt * 64;
    long long bh = (long long)(b * H + h);
    int ntiles = qt + 1;

    int jrow0 = tid & 63, jsel0 = tid >> 6;
    int jrow1 = jrow0, jsel1 = jsel0 + 2;

    auto loadTile = [&](int kt2, int st) {
        int kv0 = kt2 * 64;
        bf16* base = sT + st * (4 * FTILE);
        {
            const bf16* src = (jsel0 == 0) ? kh + (bh * Tlen + kv0 + jrow0) * HD
                                           : kl + (bh * Tlen + kv0 + jrow0) * HD;
            bf16* db = base + jsel0 * FTILE;
            unsigned dst = sptr(db) + (unsigned)(jrow0 * FAST) * 2u;
#pragma unroll
            for (int j = 0; j < 8; j++)
                asm volatile("cp.async.cg.shared.global [%0], [%1], 16;"
                             :: "r"(dst + j * 16), "l"(src + j * 8));
        }
        {
            const bf16* src = (jsel1 == 2) ? vth + (bh * HD + jrow1) * Tlen + kv0
                                           : vtl + (bh * HD + jrow1) * Tlen + kv0;
            bf16* db = base + jsel1 * FTILE;
            unsigned dst = sptr(db) + (unsigned)(jrow1 * FAST) * 2u;
#pragma unroll
            for (int j = 0; j < 8; j++)
                asm volatile("cp.async.cg.shared.global [%0], [%1], 16;"
                             :: "r"(dst + j * 16), "l"(src + j * 8));
        }
    };

    {
        int row = tid & 63;
        const bf16* src = ((tid >> 6) ? ql : qh) + (bh * Tlen + q0 + row) * HD;
        bf16* db = (tid >> 6) ? sQl : sQh;
        unsigned dst = sptr(db) + (unsigned)(row * FAST) * 2u;
#pragma unroll
        for (int j = 0; j < 8; j++)
            asm volatile("cp.async.cg.shared.global [%0], [%1], 16;"
                         :: "r"(dst + j * 16), "l"(src + j * 8));
    }
    asm volatile("cp.async.commit_group;");
    loadTile(0, 0);
    asm volatile("cp.async.commit_group;");

    asm volatile("cp.async.wait_group 1;");
    __syncthreads();

    unsigned aQh[4][4], aQl[4][4];
    {
        int arow = w * 16 + (lane & 15);
        int acol8 = (lane >> 4) << 3;
        unsigned qaH = sptr(sQh) + (unsigned)(arow * FAST + acol8) * 2;
        unsigned qaL = sptr(sQl) + (unsigned)(arow * FAST + acol8) * 2;
#pragma unroll
        for (int kk = 0; kk < 4; kk++) {
            ldsm4(aQh[kk], qaH + kk * 32);
            ldsm4(aQl[kk], qaL + kk * 32);
        }
    }

    int brow_off = (lane & 7) + ((lane & 16) ? 8 : 0);
    int bcol_off = (lane & 8) ? 8 : 0;
    unsigned bofs = (unsigned)(brow_off * FAST + bcol_off) * 2;
    unsigned kbH0 = sptr(sT) + bofs;
    unsigned kbL0 = kbH0 + FTILE * 2;
    unsigned vbH0 = kbH0 + 2 * FTILE * 2;
    unsigned vbL0 = kbH0 + 3 * FTILE * 2;
    const unsigned PSTEP = 16u * FAST * 2u;
    const unsigned SSTEP = 4u * FTILE * 2u;

    float of[8][4];
#pragma unroll
    for (int nj = 0; nj < 8; nj++)
#pragma unroll
        for (int r = 0; r < 4; r++) of[nj][r] = 0.f;
    float ls0 = 0.f, ls1 = 0.f;

    int qg0 = q0 + w * 16 + g;
    int qg1 = qg0 + 8;

    for (int kt = 0; kt < ntiles; kt++) {
        int s = kt & 1;
        int kv0 = kt * 64;

        asm volatile("cp.async.wait_group 0;");
        __syncthreads();

        int ktn = (kt + 1 < ntiles) ? kt + 1 : kt;
        loadTile(ktn, s ^ 1);
        asm volatile("cp.async.commit_group;");

        unsigned so = (unsigned)s * SSTEP;
        unsigned kbH = kbH0 + so, kbL = kbL0 + so;
        unsigned vbH = vbH0 + so, vbL = vbL0 + so;

        float c[8][4];
#pragma unroll
        for (int nj = 0; nj < 8; nj++)
#pragma unroll
            for (int r = 0; r < 4; r++) c[nj][r] = 0.f;

#pragma unroll
        for (int kk = 0; kk < 4; kk++) {
            unsigned bhf[8][2], blf[8][2], t[4];
#pragma unroll
            for (int p = 0; p < 4; p++) {
                ldsm4(t, kbH + p * PSTEP + kk * 32);
                bhf[2 * p][0] = t[0]; bhf[2 * p][1] = t[1];
                bhf[2 * p + 1][0] = t[2]; bhf[2 * p + 1][1] = t[3];
                ldsm4(t, kbL + p * PSTEP + kk * 32);
                blf[2 * p][0] = t[0]; blf[2 * p][1] = t[1];
                blf[2 * p + 1][0] = t[2]; blf[2 * p + 1][1] = t[3];
            }
#pragma unroll
            for (int nj = 0; nj < 8; nj++) {
                mma_bf16(c[nj], aQh[kk], bhf[nj]);
                mma_bf16(c[nj], aQh[kk], blf[nj]);
                mma_bf16(c[nj], aQl[kk], bhf[nj]);
            }
        }

        bool diag = (kt == qt);
#pragma unroll
        for (int nj = 0; nj < 8; nj++) {
            int colb = kv0 + 8 * nj + 2 * tig;
            float p0 = __expf(c[nj][0]);
            float p1 = __expf(c[nj][1]);
            float p2 = __expf(c[nj][2]);
            float p3 = __expf(c[nj][3]);
            if (diag) {
                if (colb > qg0)     p0 = 0.f;
                if (colb + 1 > qg0) p1 = 0.f;
                if (colb > qg1)     p2 = 0.f;
                if (colb + 1 > qg1) p3 = 0.f;
            }
            c[nj][0] = p0; c[nj][1] = p1; c[nj][2] = p2; c[nj][3] = p3;
            ls0 += p0 + p1;
            ls1 += p2 + p3;
        }

#pragma unroll
        for (int kk = 0; kk < 4; kk++) {
            unsigned aph[4], apl[4];
            aph[0] = packbf(c[2 * kk][0], c[2 * kk][1]);
            aph[1] = packbf(c[2 * kk][2], c[2 * kk][3]);
            aph[2] = packbf(c[2 * kk + 1][0], c[2 * kk + 1][1]);
            aph[3] = packbf(c[2 * kk + 1][2], c[2 * kk + 1][3]);
            apl[0] = packbf(lof(c[2 * kk][0]), lof(c[2 * kk][1]));
            apl[1] = packbf(lof(c[2 * kk][2]), lof(c[2 * kk][3]));
            apl[2] = packbf(lof(c[2 * kk + 1][0]), lof(c[2 * kk + 1][1]));
            apl[3] = packbf(lof(c[2 * kk + 1][2]), lof(c[2 * kk + 1][3]));

            unsigned vh[8][2], vl[8][2], t[4];
#pragma unroll
            for (int p = 0; p < 4; p++) {
                ldsm4(t, vbH + p * PSTEP + kk * 32);
                vh[2 * p][0] = t[0]; vh[2 * p][1] = t[1];
                vh[2 * p + 1][0] = t[2]; vh[2 * p + 1][1] = t[3];
                ldsm4(t, vbL + p * PSTEP + kk * 32);
                vl[2 * p][0] = t[0]; vl[2 * p][1] = t[1];
                vl[2 * p + 1][0] = t[2]; vl[2 * p + 1][1] = t[3];
            }
#pragma unroll
            for (int nj = 0; nj < 8; nj++) {
                mma_bf16(of[nj], aph, vh[nj]);
                mma_bf16(of[nj], apl, vh[nj]);
                mma_bf16(of[nj], aph, vl[nj]);
            }
        }
    }

    ls0 += __shfl_xor_sync(0xFFFFFFFFu, ls0, 1);
    ls0 += __shfl_xor_sync(0xFFFFFFFFu, ls0, 2);
    ls1 += __shfl_xor_sync(0xFFFFFFFFu, ls1, 1);
    ls1 += __shfl_xor_sync(0xFFFFFFFFu, ls1, 2);
    float inv0 = 1.f / ls0;
    float inv1 = 1.f / ls1;

    long long r0 = (long long)(b * Tlen + qg0) * C + h * HD;
    long long r1 = (long long)(b * Tlen + qg1) * C + h * HD;
#pragma unroll
    for (int nj = 0; nj < 8; nj++) {
        int col = 8 * nj + 2 * tig;
        *(__half2*)&out[r0 + col] = __floats2half2_rn(of[nj][0] * inv0, of[nj][1] * inv0);
        *(__half2*)&out[r1 + col] = __floats2half2_rn(of[nj][2] * inv1, of[nj][3] * inv1);
    }
}

// ---------------- driver ----------------
#define HG_SMEM(BM) (3 * ((BM) * HST + 128 * HST) * (int)sizeof(__half))
#define ATTN_SMEM ((2 + 8) * FTILE * (int)sizeof(bf16))

extern "C" void kernel_launch(void* const* d_in, const int* in_sizes, int n_in,
                              void* d_out, int out_size) {
    const int*   idx      = (const int*)  d_in[0];
    const float* wte      = (const float*)d_in[1];
    const float* wpe      = (const float*)d_in[2];
    const float* ln1_w    = (const float*)d_in[3];
    const float* ln1_b    = (const float*)d_in[4];
    const float* attn_w   = (const float*)d_in[5];
    const float* attn_b   = (const float*)d_in[6];
    const float* proj_w   = (const float*)d_in[7];
    const float* proj_b   = (const float*)d_in[8];
    const float* ln2_w    = (const float*)d_in[9];
    const float* ln2_b    = (const float*)d_in[10];
    const float* fc_w     = (const float*)d_in[11];
    const float* fc_b     = (const float*)d_in[12];
    const float* fcproj_w = (const float*)d_in[13];
    const float* fcproj_b = (const float*)d_in[14];
    const float* lnf_w    = (const float*)d_in[15];
    const float* lnf_b    = (const float*)d_in[16];
    const float* lm_head  = (const float*)d_in[17];
    float* out = (float*)d_out;

    float *x;
    __half *ln, *atty, *hbuf, *wq, *wp, *wf, *wfp, *wlm;
    bf16 *qh, *ql, *kh, *kl, *vth, *vtl;
    cudaGetSymbolAddress((void**)&x,    g_x);
    cudaGetSymbolAddress((void**)&ln,   g_ln);
    cudaGetSymbolAddress((void**)&atty, g_atty);
    cudaGetSymbolAddress((void**)&hbuf, g_h);
    cudaGetSymbolAddress((void**)&wq,   g_wqkv);
    cudaGetSymbolAddress((void**)&wp,   g_wproj);
    cudaGetSymbolAddress((void**)&wf,   g_wfc);
    cudaGetSymbolAddress((void**)&wfp,  g_wfp);
    cudaGetSymbolAddress((void**)&wlm,  g_wlm);
    cudaGetSymbolAddress((void**)&qh,   g_qh);
    cudaGetSymbolAddress((void**)&ql,   g_ql);
    cudaGetSymbolAddress((void**)&kh,   g_kh);
    cudaGetSymbolAddress((void**)&kl,   g_kl);
    cudaGetSymbolAddress((void**)&vth,  g_vth);
    cudaGetSymbolAddress((void**)&vtl,  g_vtl);

    cudaFuncSetAttribute(hgemm_kernel<128>,
                         cudaFuncAttributeMaxDynamicSharedMemorySize, HG_SMEM(128));
    cudaFuncSetAttribute(hgemm_kernel<64>,
                         cudaFuncAttributeMaxDynamicSharedMemorySize, HG_SMEM(64));
    cudaFuncSetAttribute(fattn_kernel,
                         cudaFuncAttributeMaxDynamicSharedMemorySize, ATTN_SMEM);

    // one-time weight transpose + fp16 conversion
    dim3 tb(32, 8);
    transw_kernel<<<dim3(C3 / 32, C / 32, NL), tb>>>(attn_w, wq, C, C3,
        (long long)C * C3, (long long)C3 * C);
    transw_kernel<<<dim3(C / 32, C / 32, NL), tb>>>(proj_w, wp, C, C,
        (long long)C * C, (long long)C * C);
    transw_kernel<<<dim3(C4 / 32, C / 32, NL), tb>>>(fc_w, wf, C, C4,
        (long long)C * C4, (long long)C4 * C);
    transw_kernel<<<dim3(C / 32, C4 / 32, NL), tb>>>(fcproj_w, wfp, C4, C,
        (long long)C4 * C, (long long)C * C4);
    transw_kernel<<<dim3(VP / 32, C / 32, 1), tb>>>(lm_head, wlm, C, V, 0, 0);

    embed_kernel<<<BT, 256>>>(idx, wte, wpe, x);

    for (int l = 0; l < NL; l++) {
        ln_kernel<<<BT, 256>>>(x, ln1_w + l * C, ln1_b + l * C, ln);
        hgemm_kernel<128><<<dim3(C3 / 128, BT / 128), 256, HG_SMEM(128)>>>(
            ln, wq + (long long)l * C3 * C, attn_b + l * C3, nullptr, nullptr,
            BT, C3, C, 4, qh, ql, kh, kl, vth, vtl);
        fattn_kernel<<<dim3(Tlen / 64, H, Bsz), 128, ATTN_SMEM>>>(
            qh, ql, kh, kl, vth, vtl, atty);
        hgemm_kernel<64><<<dim3(C / 128, BT / 64), 256, HG_SMEM(64)>>>(
            atty, wp + (long long)l * C * C, proj_b + l * C, x, nullptr,
            BT, C, C, 2, nullptr, nullptr, nullptr, nullptr, nullptr, nullptr);
        ln_kernel<<<BT, 256>>>(x, ln2_w + l * C, ln2_b + l * C, ln);
        hgemm_kernel<128><<<dim3(C4 / 128, BT / 128), 256, HG_SMEM(128)>>>(
            ln, wf + (long long)l * C4 * C, fc_b + l * C4, nullptr, hbuf,
            BT, C4, C, 1, nullptr, nullptr, nullptr, nullptr, nullptr, nullptr);
        hgemm_kernel<64><<<dim3(C / 128, BT / 64), 256, HG_SMEM(64)>>>(
            hbuf, wfp + (long long)l * C * C4, fcproj_b + l * C, x, nullptr,
            BT, C, C4, 2, nullptr, nullptr, nullptr, nullptr, nullptr, nullptr);
    }

    ln_kernel<<<BT, 256>>>(x, lnf_w, lnf_b, ln);
    hgemm_kernel<128><<<dim3(VP / 128, BT / 128), 256, HG_SMEM(128)>>>(
        ln, wlm, (const float*)nullptr, out, nullptr,
        BT, V, C, 3, nullptr, nullptr, nullptr, nullptr, nullptr, nullptr);
}